// round 10
// baseline (speedup 1.0000x reference)
#include <cuda_runtime.h>
#include <cuda_bf16.h>
#include <math.h>
#include <stdint.h>

// ConLoss (NT-Xent): z = normalize(concat(h1,h2)) [8192,512]; sim = z z^T; T=0.5
// loss_i = -2*sim[i,i^4096] + log(sum_{j!=i} exp(2*sim_ij)); out = mean.
// Round 10: e4m3 mma.sync; 512 threads / 16 warps (warp tile 32x64) to kill
// register spills (was 255 regs) and double per-SMSP warps; XOR-advanced
// swizzled ldmatrix bases; 3-stage cp.async pipeline; fused last-CTA loss.

#define NROWS 8192
#define HALF  4096
#define D     512

#define THREADS 512
#define BM 128
#define BN 256
#define BK 128                       // fp8 elems per chunk (128 B/row)
#define NKC (D / BK)                 // 4 chunks per column tile
#define CGRPS 2
#define CT_PER (NROWS / BN / CGRPS)  // 16 column tiles per CTA
#define TC (CT_PER * NKC)            // 64 chunks
#define TOTAL_CTAS ((NROWS / BM) * CGRPS)  // 128

#define ACH_BYTES (128 * 128)        // 16 KB A chunk
#define BST_BYTES (BN * 128)         // 32 KB B stage
#define SMEM_A 0                     // 4 chunks resident = 64 KB
#define SMEM_B (NKC * ACH_BYTES)     // 65536; 3 stages of 32 KB
#define SMEM_TOTAL (SMEM_B + 3 * BST_BYTES)  // 163840

// exp(2*sim) = 2^(acc * 2*log2e/256), acc = 256*sim
#define EXP_SCALE 0.0112710550f
#define POS_SCALE 0.0078125f         // 2/256

__device__ __align__(16) uint8_t g_z8[NROWS * D];
__device__ float g_S[NROWS];
__device__ float g_pos[NROWS];
__device__ unsigned int g_cnt = 0;

// ---------------- helpers ----------------
__device__ __forceinline__ uint32_t smem_u32(const void* p) {
    uint32_t a;
    asm("{ .reg .u64 t; cvta.to.shared.u64 t, %1; cvt.u32.u64 %0, t; }" : "=r"(a) : "l"(p));
    return a;
}
__device__ __forceinline__ uint32_t SWZ(uint32_t off) {   // SW128 swizzle
    return off ^ ((off >> 3) & 0x70);
}
__device__ __forceinline__ void cp16(uint32_t dst, const void* src) {
    asm volatile("cp.async.cg.shared.global [%0], [%1], 16;" :: "r"(dst), "l"(src));
}
#define CP_COMMIT() asm volatile("cp.async.commit_group;" ::: "memory")
#define CP_WAIT(n)  asm volatile("cp.async.wait_group %0;" :: "n"(n) : "memory")

__device__ __forceinline__ void ldmx4(uint32_t* r, uint32_t addr) {
    asm volatile("ldmatrix.sync.aligned.m8n8.x4.shared.b16 {%0,%1,%2,%3}, [%4];"
                 : "=r"(r[0]), "=r"(r[1]), "=r"(r[2]), "=r"(r[3]) : "r"(addr));
}
__device__ __forceinline__ void mma_fp8(float* c, const uint32_t* a, const uint32_t* b) {
    asm volatile("mma.sync.aligned.m16n8k32.row.col.f32.e4m3.e4m3.f32 "
                 "{%0,%1,%2,%3}, {%4,%5,%6,%7}, {%8,%9}, {%0,%1,%2,%3};"
                 : "+f"(c[0]), "+f"(c[1]), "+f"(c[2]), "+f"(c[3])
                 : "r"(a[0]), "r"(a[1]), "r"(a[2]), "r"(a[3]), "r"(b[0]), "r"(b[1]));
}
__device__ __forceinline__ float ex2f(float x) {
    float y;
    asm("ex2.approx.f32 %0, %1;" : "=f"(y) : "f"(x));
    return y;
}
__device__ __forceinline__ uint32_t pack_e4m3(float f0, float f1, float f2, float f3) {
    uint16_t lo, hi;
    asm("cvt.rn.satfinite.e4m3x2.f32 %0, %1, %2;" : "=h"(lo) : "f"(f1), "f"(f0));
    asm("cvt.rn.satfinite.e4m3x2.f32 %0, %1, %2;" : "=h"(hi) : "f"(f3), "f"(f2));
    return (uint32_t)lo | ((uint32_t)hi << 16);
}

// ---------------- kernels ----------------
// One warp per row: normalize, scale by 16, write e4m3. Also zeroes g_S.
__global__ void norm_kernel(const float* __restrict__ a, const float* __restrict__ b) {
    int gt = blockIdx.x * blockDim.x + threadIdx.x;
    if (gt < NROWS) g_S[gt] = 0.0f;
    int gw   = gt >> 5;
    int lane = threadIdx.x & 31;
    if (gw >= NROWS) return;
    const float* src = (gw < HALF) ? (a + (size_t)gw * D) : (b + (size_t)(gw - HALF) * D);
    const float4* s4 = (const float4*)src;
    float4 v[4];
    float ss = 0.0f;
#pragma unroll
    for (int l = 0; l < 4; l++) {
        v[l] = s4[lane + l * 32];
        ss += v[l].x * v[l].x + v[l].y * v[l].y + v[l].z * v[l].z + v[l].w * v[l].w;
    }
#pragma unroll
    for (int m = 16; m; m >>= 1) ss += __shfl_xor_sync(0xffffffffu, ss, m);
    float inv = 16.0f / fmaxf(sqrtf(ss), 1e-8f);
    uint32_t* d32 = (uint32_t*)(g_z8 + (size_t)gw * D);
#pragma unroll
    for (int l = 0; l < 4; l++) {
        float4 w = v[l];
        d32[lane + 32 * l] = pack_e4m3(w.x * inv, w.y * inv, w.z * inv, w.w * inv);
    }
}

// grid (64 row tiles, 2 col groups), 512 threads = 16 warps (4 row x 4 col).
// Warp tile 32x64. Last CTA out computes the final loss.
__global__ __launch_bounds__(THREADS, 1) void gemm_kernel(float* __restrict__ out) {
    extern __shared__ __align__(1024) char smem[];
    const uint32_t sb = smem_u32(smem);
    const int tid  = threadIdx.x;
    const int wid  = tid >> 5;
    const int lane = tid & 31;
    const int wm = wid & 3;        // row warp: 32 rows
    const int wn = wid >> 2;       // col warp: 64 cols
    const int row_base = blockIdx.x * BM;
    const int cg = blockIdx.y;

    const uint4* Z4 = (const uint4*)g_z8;   // 32 uint4 per row

    // Resident A tile: 64 KB = 4096 cp16 (8/thread), SW128 per 16KB chunk.
#pragma unroll
    for (int l = 0; l < 8; l++) {
        int idx = tid + l * THREADS;
        int c = idx >> 10, w = idx & 1023, row = w >> 3, g = w & 7;
        cp16(sb + SMEM_A + c * ACH_BYTES + SWZ(row * 128 + g * 16),
             Z4 + (size_t)(row_base + row) * 32 + c * 8 + g);
    }
    // First two B chunks (2048 cp16 each, 4/thread).
    const int cb0 = cg * CT_PER * BN;
#pragma unroll
    for (int l = 0; l < 4; l++) {
        int idx = tid + l * THREADS;
        int row = idx >> 3, g = idx & 7;
        cp16(sb + SMEM_B + SWZ(row * 128 + g * 16),
             Z4 + (size_t)(cb0 + row) * 32 + g);
    }
    CP_COMMIT();   // group: A + chunk0
#pragma unroll
    for (int l = 0; l < 4; l++) {
        int idx = tid + l * THREADS;
        int row = idx >> 3, g = idx & 7;
        cp16(sb + SMEM_B + BST_BYTES + SWZ(row * 128 + g * 16),
             Z4 + (size_t)(cb0 + row) * 32 + 8 + g);
    }
    CP_COMMIT();   // group: chunk1

    // Precomputed swizzled ldmatrix bases; advance along k by XOR (SW128 only
    // mixes bits 7-9 into 4-6, and k-offsets live in bits 4-6).
    const int a_row0 = wm * 32 + (lane & 15);
    const uint32_t a_off0 = SWZ(a_row0 * 128 + (lane >> 4) * 16);
    const uint32_t a_off1 = SWZ((a_row0 + 16) * 128 + (lane >> 4) * 16);
    const int b_row0 = wn * 64 + (lane & 7) + ((lane & 16) ? 8 : 0);
    uint32_t b_off[4];
#pragma unroll
    for (int q = 0; q < 4; q++)
        b_off[q] = SWZ((b_row0 + q * 16) * 128 + ((lane & 8) ? 16 : 0));

    // epilogue mapping
    const int ep_r0 = row_base + wm * 32 + (lane >> 2);  // + mf*16 + h*8
    const int ep_c0 = (lane & 3) * 2;

    float rowsum[2][2];
    rowsum[0][0] = rowsum[0][1] = rowsum[1][0] = rowsum[1][1] = 0.0f;

    int ic = 0;
    for (int ct = 0; ct < CT_PER; ct++) {
        const int col_base = (cg * CT_PER + ct) * BN;
        float c[2][8][4];
#pragma unroll
        for (int mf = 0; mf < 2; mf++)
#pragma unroll
            for (int nf = 0; nf < 8; nf++)
#pragma unroll
                for (int e = 0; e < 4; e++) c[mf][nf][e] = 0.0f;

#pragma unroll 1
        for (int kc = 0; kc < NKC; kc++, ic++) {
            CP_WAIT(1);            // chunk ic resident
            __syncthreads();       // publish + guard stage reuse (dist 2, 3 stages)
            const int inx = ic + 2;
            if (inx < TC) {
                const int nct = inx >> 2, nkc = inx & 3;
                const int ncol = (cg * CT_PER + nct) * BN;
                const uint32_t dst = sb + SMEM_B + (inx % 3) * BST_BYTES;
#pragma unroll
                for (int l = 0; l < 4; l++) {
                    int idx = tid + l * THREADS;
                    int row = idx >> 3, g = idx & 7;
                    cp16(dst + SWZ(row * 128 + g * 16),
                         Z4 + (size_t)(ncol + row) * 32 + nkc * 8 + g);
                }
                CP_COMMIT();
            }

            const uint32_t Ab = sb + SMEM_A + kc * ACH_BYTES;
            const uint32_t Bb = sb + SMEM_B + (ic % 3) * BST_BYTES;
#pragma unroll
            for (int k32 = 0; k32 < 4; k32++) {
                const uint32_t cb = k32 * 32;
                uint32_t af[2][4];
                ldmx4(af[0], Ab + (a_off0 ^ cb));
                ldmx4(af[1], Ab + (a_off1 ^ cb));
#pragma unroll
                for (int q = 0; q < 4; q++) {
                    uint32_t bf[4];
                    ldmx4(bf, Bb + (b_off[q] ^ cb));
                    mma_fp8(c[0][q * 2 + 0], af[0], &bf[0]);
                    mma_fp8(c[0][q * 2 + 1], af[0], &bf[2]);
                    mma_fp8(c[1][q * 2 + 0], af[1], &bf[0]);
                    mma_fp8(c[1][q * 2 + 1], af[1], &bf[2]);
                }
            }
        }

        // epilogue: positives, diagonal exclusion, exp row-sums (MUFU ex2)
#pragma unroll
        for (int mf = 0; mf < 2; mf++)
#pragma unroll
            for (int h = 0; h < 2; h++) {
                const int r = ep_r0 + mf * 16 + h * 8;
                float acc = 0.0f;
#pragma unroll
                for (int nf = 0; nf < 8; nf++)
#pragma unroll
                    for (int e = 0; e < 2; e++) {
                        const int cidx = col_base + wn * 64 + nf * 8 + ep_c0 + e;
                        const float sv = c[mf][nf][h * 2 + e];
                        if (cidx == (r ^ HALF)) g_pos[r] = sv;
                        acc += (cidx == r) ? 0.0f : ex2f(sv * EXP_SCALE);
                    }
                rowsum[mf][h] += acc;
            }
    }

    // reduce the 4 lanes sharing each row; one atomic per row per warp
#pragma unroll
    for (int mf = 0; mf < 2; mf++)
#pragma unroll
        for (int h = 0; h < 2; h++) {
            float v = rowsum[mf][h];
            v += __shfl_xor_sync(0xffffffffu, v, 1);
            v += __shfl_xor_sync(0xffffffffu, v, 2);
            if ((lane & 3) == 0) atomicAdd(&g_S[ep_r0 + mf * 16 + h * 8], v);
        }

    // ---- fused final loss: last CTA to finish reduces g_S / g_pos ----
    __threadfence();
    __shared__ unsigned int s_last;
    __syncthreads();
    if (tid == 0) s_last = atomicAdd(&g_cnt, 1u);
    __syncthreads();
    if (s_last == TOTAL_CTAS - 1) {
        __threadfence();
        float acc = 0.0f;
        for (int i = tid; i < NROWS; i += THREADS)
            acc += -POS_SCALE * g_pos[i] + logf(g_S[i]);
#pragma unroll
        for (int m = 16; m; m >>= 1) acc += __shfl_xor_sync(0xffffffffu, acc, m);
        __shared__ float red[16];
        if (lane == 0) red[wid] = acc;
        __syncthreads();
        if (tid == 0) {
            float v = 0.0f;
#pragma unroll
            for (int w = 0; w < 16; w++) v += red[w];
            out[0] = v * (1.0f / NROWS);
            g_cnt = 0;   // reset for next graph replay
        }
    }
}

extern "C" void kernel_launch(void* const* d_in, const int* in_sizes, int n_in,
                              void* d_out, int out_size) {
    const float* a = (const float*)d_in[0];
    const float* b = (const float*)d_in[1];
    (void)in_sizes; (void)n_in; (void)out_size;

    cudaFuncSetAttribute(gemm_kernel, cudaFuncAttributeMaxDynamicSharedMemorySize, SMEM_TOTAL);

    norm_kernel<<<NROWS / 8, 256>>>(a, b);
    dim3 grid(NROWS / BM, CGRPS);
    gemm_kernel<<<grid, THREADS, SMEM_TOTAL>>>((float*)d_out);
}

// round 11
// speedup vs baseline: 2.0568x; 2.0568x over previous
#include <cuda_runtime.h>
#include <cuda_bf16.h>
#include <math.h>
#include <stdint.h>

// ConLoss (NT-Xent): z = normalize(concat(h1,h2)) [8192,512]; sim = z z^T; T=0.5
// loss_i = -2*sim[i,i^4096] + log(sum_{j!=i} exp(2*sim_ij)); out = mean.
// Round 11: SYMMETRY — sim is symmetric, compute only upper-triangle tiles
// (2080 of 4096), each off-diag tile feeds row sums AND (transposed) col sums.
// Tensor work halves. e4m3 mma.sync, 2-stage cp.async ring, 2 CTAs/SM.

#define NROWS 8192
#define HALF  4096
#define D     512

#define THREADS 256
#define BT 128                        // tile dim (both row & col)
#define NT (NROWS / BT)               // 64 tile rows
#define NTILES (NT * (NT + 1) / 2)    // 2080
#define BK 128                        // fp8 k per chunk (128 B/row)
#define NKC (D / BK)                  // 4 chunks

#define CH_BYTES (BT * 128)           // 16 KB per operand chunk
#define STAGE_BYTES (2 * CH_BYTES)    // A chunk + B chunk = 32 KB
#define SMEM_TOTAL (2 * STAGE_BYTES)  // 2 stages = 64 KB

// exp(2*sim) = 2^(acc * 2*log2e/256), acc = 256*sim (z scaled by 16)
#define EXP_SCALE 0.0112710550f
#define POS_SCALE 0.0078125f          // 2/256

__device__ __align__(16) uint8_t g_z8[NROWS * D];
__device__ float g_S[NROWS];
__device__ float g_pos[NROWS];
__device__ unsigned int g_cnt = 0;

// ---------------- helpers ----------------
__device__ __forceinline__ uint32_t smem_u32(const void* p) {
    uint32_t a;
    asm("{ .reg .u64 t; cvta.to.shared.u64 t, %1; cvt.u32.u64 %0, t; }" : "=r"(a) : "l"(p));
    return a;
}
__device__ __forceinline__ uint32_t SWZ(uint32_t off) {   // SW128 swizzle
    return off ^ ((off >> 3) & 0x70);
}
__device__ __forceinline__ void cp16(uint32_t dst, const void* src) {
    asm volatile("cp.async.cg.shared.global [%0], [%1], 16;" :: "r"(dst), "l"(src));
}
#define CP_COMMIT() asm volatile("cp.async.commit_group;" ::: "memory")
#define CP_WAIT(n)  asm volatile("cp.async.wait_group %0;" :: "n"(n) : "memory")

__device__ __forceinline__ void ldmx4(uint32_t* r, uint32_t addr) {
    asm volatile("ldmatrix.sync.aligned.m8n8.x4.shared.b16 {%0,%1,%2,%3}, [%4];"
                 : "=r"(r[0]), "=r"(r[1]), "=r"(r[2]), "=r"(r[3]) : "r"(addr));
}
__device__ __forceinline__ void mma_fp8(float* c, const uint32_t* a, const uint32_t* b) {
    asm volatile("mma.sync.aligned.m16n8k32.row.col.f32.e4m3.e4m3.f32 "
                 "{%0,%1,%2,%3}, {%4,%5,%6,%7}, {%8,%9}, {%0,%1,%2,%3};"
                 : "+f"(c[0]), "+f"(c[1]), "+f"(c[2]), "+f"(c[3])
                 : "r"(a[0]), "r"(a[1]), "r"(a[2]), "r"(a[3]), "r"(b[0]), "r"(b[1]));
}
__device__ __forceinline__ float ex2f(float x) {
    float y;
    asm("ex2.approx.f32 %0, %1;" : "=f"(y) : "f"(x));
    return y;
}
__device__ __forceinline__ uint32_t pack_e4m3(float f0, float f1, float f2, float f3) {
    uint16_t lo, hi;
    asm("cvt.rn.satfinite.e4m3x2.f32 %0, %1, %2;" : "=h"(lo) : "f"(f1), "f"(f0));
    asm("cvt.rn.satfinite.e4m3x2.f32 %0, %1, %2;" : "=h"(hi) : "f"(f3), "f"(f2));
    return (uint32_t)lo | ((uint32_t)hi << 16);
}

// ---------------- kernels ----------------
// One warp per row: normalize, scale by 16, write e4m3. Also zeroes g_S.
__global__ void norm_kernel(const float* __restrict__ a, const float* __restrict__ b) {
    int gt = blockIdx.x * blockDim.x + threadIdx.x;
    if (gt < NROWS) g_S[gt] = 0.0f;
    int gw   = gt >> 5;
    int lane = threadIdx.x & 31;
    if (gw >= NROWS) return;
    const float* src = (gw < HALF) ? (a + (size_t)gw * D) : (b + (size_t)(gw - HALF) * D);
    const float4* s4 = (const float4*)src;
    float4 v[4];
    float ss = 0.0f;
#pragma unroll
    for (int l = 0; l < 4; l++) {
        v[l] = s4[lane + l * 32];
        ss += v[l].x * v[l].x + v[l].y * v[l].y + v[l].z * v[l].z + v[l].w * v[l].w;
    }
#pragma unroll
    for (int m = 16; m; m >>= 1) ss += __shfl_xor_sync(0xffffffffu, ss, m);
    float inv = 16.0f / fmaxf(sqrtf(ss), 1e-8f);
    uint32_t* d32 = (uint32_t*)(g_z8 + (size_t)gw * D);
#pragma unroll
    for (int l = 0; l < 4; l++) {
        float4 w = v[l];
        d32[lane + 32 * l] = pack_e4m3(w.x * inv, w.y * inv, w.z * inv, w.w * inv);
    }
}

// One CTA per upper-triangle tile pair (rt, ct), ct >= rt. 256 thr = 8 warps (4x2).
__global__ __launch_bounds__(THREADS, 2) void gemm_kernel(float* __restrict__ out) {
    extern __shared__ __align__(1024) char smem[];
    const uint32_t sb = smem_u32(smem);
    const int tid  = threadIdx.x;
    const int wid  = tid >> 5;
    const int lane = tid & 31;
    const int wm = wid & 3;        // row warp: 32 rows
    const int wn = wid >> 2;       // col warp: 64 cols

    // decode flat tile index -> (rt, ct), ct >= rt
    const int flat = blockIdx.x;
    int rt = (int)((2 * NT + 1 - sqrtf((float)((2 * NT + 1) * (2 * NT + 1) - 8 * flat))) * 0.5f);
    while (rt * (2 * NT + 1 - rt) / 2 > flat) rt--;
    while ((rt + 1) * (2 * NT - rt) / 2 <= flat) rt++;
    const int ct = rt + (flat - rt * (2 * NT + 1 - rt) / 2);
    const int row_base = rt * BT;
    const int col_base = ct * BT;
    const bool diag = (rt == ct);

    const uint4* Z4 = (const uint4*)g_z8;   // 32 uint4 per row

    // prologue: load chunk 0 (A rows + B rows), 2048 cp16 / 256 thr = 8 each
#pragma unroll
    for (int l = 0; l < 4; l++) {
        int idx = tid + l * THREADS;
        int row = idx >> 3, g = idx & 7;
        cp16(sb + SWZ(row * 128 + g * 16), Z4 + (size_t)(row_base + row) * 32 + g);
        cp16(sb + CH_BYTES + SWZ(row * 128 + g * 16), Z4 + (size_t)(col_base + row) * 32 + g);
    }
    CP_COMMIT();

    // ldmatrix lane addressing (XOR-advance along k: offsets live in bits 4-6)
    const int a_row0 = wm * 32 + (lane & 15);
    const uint32_t a_off0 = SWZ(a_row0 * 128 + (lane >> 4) * 16);
    const uint32_t a_off1 = SWZ((a_row0 + 16) * 128 + (lane >> 4) * 16);
    const int b_row0 = wn * 64 + (lane & 7) + ((lane & 16) ? 8 : 0);
    uint32_t b_off[4];
#pragma unroll
    for (int q = 0; q < 4; q++)
        b_off[q] = SWZ((b_row0 + q * 16) * 128 + ((lane & 8) ? 16 : 0));

    float c[2][8][4];
#pragma unroll
    for (int mf = 0; mf < 2; mf++)
#pragma unroll
        for (int nf = 0; nf < 8; nf++)
#pragma unroll
            for (int e = 0; e < 4; e++) c[mf][nf][e] = 0.0f;

#pragma unroll
    for (int kc = 0; kc < NKC; kc++) {
        CP_WAIT(0);            // chunk kc resident
        __syncthreads();       // all warps done with the other stage
        if (kc + 1 < NKC) {    // prefetch next chunk into freed stage
            const uint32_t dst = sb + ((kc + 1) & 1) * STAGE_BYTES;
#pragma unroll
            for (int l = 0; l < 4; l++) {
                int idx = tid + l * THREADS;
                int row = idx >> 3, g = idx & 7;
                cp16(dst + SWZ(row * 128 + g * 16),
                     Z4 + (size_t)(row_base + row) * 32 + (kc + 1) * 8 + g);
                cp16(dst + CH_BYTES + SWZ(row * 128 + g * 16),
                     Z4 + (size_t)(col_base + row) * 32 + (kc + 1) * 8 + g);
            }
            CP_COMMIT();
        }

        const uint32_t Ab = sb + (kc & 1) * STAGE_BYTES;
        const uint32_t Bb = Ab + CH_BYTES;
#pragma unroll
        for (int k32 = 0; k32 < 4; k32++) {
            const uint32_t cb = k32 * 32;
            uint32_t af[2][4];
            ldmx4(af[0], Ab + (a_off0 ^ cb));
            ldmx4(af[1], Ab + (a_off1 ^ cb));
#pragma unroll
            for (int q = 0; q < 4; q++) {
                uint32_t bf[4];
                ldmx4(bf, Bb + (b_off[q] ^ cb));
                mma_fp8(c[0][q * 2 + 0], af[0], &bf[0]);
                mma_fp8(c[0][q * 2 + 1], af[0], &bf[2]);
                mma_fp8(c[1][q * 2 + 0], af[1], &bf[0]);
                mma_fp8(c[1][q * 2 + 1], af[1], &bf[2]);
            }
        }
    }

    // ---- epilogue: exp in place, positives, row sums, (off-diag) col sums ----
    const int ep_r0 = row_base + wm * 32 + (lane >> 2);   // + mf*16 + h*8
    const int ep_c0 = col_base + wn * 64 + (lane & 3) * 2; // + nf*8 + e

#pragma unroll
    for (int mf = 0; mf < 2; mf++)
#pragma unroll
        for (int nf = 0; nf < 8; nf++)
#pragma unroll
            for (int h = 0; h < 2; h++)
#pragma unroll
                for (int e = 0; e < 2; e++) {
                    const int r = ep_r0 + mf * 16 + h * 8;
                    const int cx = ep_c0 + nf * 8 + e;
                    const float sv = c[mf][nf][h * 2 + e];
                    if (cx == (r ^ HALF)) { g_pos[r] = sv; g_pos[cx] = sv; }
                    c[mf][nf][h * 2 + e] = (cx == r) ? 0.0f : ex2f(sv * EXP_SCALE);
                }

    // row sums: reduce over nf,e in-thread, lanes sharing a row (bits 0-1)
#pragma unroll
    for (int mf = 0; mf < 2; mf++)
#pragma unroll
        for (int h = 0; h < 2; h++) {
            float v = 0.0f;
#pragma unroll
            for (int nf = 0; nf < 8; nf++)
                v += c[mf][nf][h * 2 + 0] + c[mf][nf][h * 2 + 1];
            v += __shfl_xor_sync(0xffffffffu, v, 1);
            v += __shfl_xor_sync(0xffffffffu, v, 2);
            if ((lane & 3) == 0) atomicAdd(&g_S[ep_r0 + mf * 16 + h * 8], v);
        }

    // col sums (transpose contribution): reduce over mf,h in-thread, lanes
    // sharing a col (bits 2-4), skip on diagonal tiles (already counted).
    if (!diag) {
#pragma unroll
        for (int nf = 0; nf < 8; nf++)
#pragma unroll
            for (int e = 0; e < 2; e++) {
                float v = c[0][nf][e] + c[0][nf][2 + e] + c[1][nf][e] + c[1][nf][2 + e];
                v += __shfl_xor_sync(0xffffffffu, v, 4);
                v += __shfl_xor_sync(0xffffffffu, v, 8);
                v += __shfl_xor_sync(0xffffffffu, v, 16);
                if (lane < 4) atomicAdd(&g_S[ep_c0 + nf * 8 + e], v);
            }
    }

    // ---- fused final loss: last CTA reduces g_S / g_pos ----
    __threadfence();
    __shared__ unsigned int s_last;
    __syncthreads();
    if (tid == 0) s_last = atomicAdd(&g_cnt, 1u);
    __syncthreads();
    if (s_last == NTILES - 1) {
        __threadfence();
        float acc = 0.0f;
        for (int i = tid; i < NROWS; i += THREADS)
            acc += -POS_SCALE * g_pos[i] + logf(g_S[i]);
#pragma unroll
        for (int m = 16; m; m >>= 1) acc += __shfl_xor_sync(0xffffffffu, acc, m);
        __shared__ float red[8];
        if (lane == 0) red[wid] = acc;
        __syncthreads();
        if (tid == 0) {
            float v = 0.0f;
#pragma unroll
            for (int w = 0; w < 8; w++) v += red[w];
            out[0] = v * (1.0f / NROWS);
            g_cnt = 0;   // reset for next graph replay
        }
    }
}

extern "C" void kernel_launch(void* const* d_in, const int* in_sizes, int n_in,
                              void* d_out, int out_size) {
    const float* a = (const float*)d_in[0];
    const float* b = (const float*)d_in[1];
    (void)in_sizes; (void)n_in; (void)out_size;

    cudaFuncSetAttribute(gemm_kernel, cudaFuncAttributeMaxDynamicSharedMemorySize, SMEM_TOTAL);

    norm_kernel<<<NROWS / 8, 256>>>(a, b);
    gemm_kernel<<<NTILES, THREADS, SMEM_TOTAL>>>((float*)d_out);
}